// round 4
// baseline (speedup 1.0000x reference)
#include <cuda_runtime.h>

// TemporalExtensionShift: x [8, 256, 16, 56, 56] f32.
// One-hot depthwise dilated conv == temporal shift:
//   c in [0,32):   y[t] = x[t+2]  (0 if t+2 >= 16)
//   c in [32,64):  y[t] = x[t-2]  (0 if t-2 < 0)
//   c in [64,256): y[t] = x[t]
//
// Persistent grid-stride over planes: full-residency launch (no block-retire
// churn), block-uniform branches, MLP=4 front-batched loads, streaming hints.

#define HW4     784            // 56*56/4 float4 per (n,c,t) plane
#define T_DIM   16
#define NPLANE  32768          // 8*256*16
#define NTH     256
#define NBLK    (152 * 8)      // full residency on GB300 (152 SMs, 8 CTAs/SM)

__global__ void __launch_bounds__(NTH)
temporal_shift_kernel(const float4* __restrict__ x, float4* __restrict__ y) {
    int tid = threadIdx.x;
    bool tail = tid < (HW4 - 3 * NTH);   // 784 = 3*256 + 16

    for (int plane = blockIdx.x; plane < NPLANE; plane += NBLK) {
        int t = plane & (T_DIM - 1);
        int c = (plane >> 4) & 255;

        float4* dst = y + (long long)plane * HW4;

        const float4* src;
        bool zero = false;
        if (c < 32) {
            if (t < T_DIM - 2) src = x + (long long)(plane + 2) * HW4;
            else               zero = true;
        } else if (c < 64) {
            if (t >= 2) src = x + (long long)(plane - 2) * HW4;
            else        zero = true;
        } else {
            src = x + (long long)plane * HW4;
        }

        if (zero) {
            float4 z = make_float4(0.f, 0.f, 0.f, 0.f);
            __stcs(dst + tid,           z);
            __stcs(dst + tid + NTH,     z);
            __stcs(dst + tid + 2 * NTH, z);
            if (tail) __stcs(dst + tid + 3 * NTH, z);
            continue;
        }

        float4 v0 = __ldcs(src + tid);
        float4 v1 = __ldcs(src + tid + NTH);
        float4 v2 = __ldcs(src + tid + 2 * NTH);
        float4 v3;
        if (tail) v3 = __ldcs(src + tid + 3 * NTH);

        __stcs(dst + tid,           v0);
        __stcs(dst + tid + NTH,     v1);
        __stcs(dst + tid + 2 * NTH, v2);
        if (tail) __stcs(dst + tid + 3 * NTH, v3);
    }
}

extern "C" void kernel_launch(void* const* d_in, const int* in_sizes, int n_in,
                              void* d_out, int out_size) {
    const float4* x = (const float4*)d_in[0];   // weight d_in[1] is fixed one-hot; semantics hardcoded
    float4* y = (float4*)d_out;
    temporal_shift_kernel<<<NBLK, NTH>>>(x, y);
}

// round 5
// speedup vs baseline: 1.1310x; 1.1310x over previous
#include <cuda_runtime.h>

// TemporalExtensionShift: x [8, 256, 16, 56, 56] f32.
// One-hot depthwise dilated conv == temporal shift by +-2 t (or identity/zero).
// A shift of 2 timesteps == exactly one t-PAIR. Branch classes are uniform
// over t-pairs {0,1},{2,3},...,{14,15}. Block per (n,c,t-pair):
//   c in [0,32):   dst pair p <- src pair p+1   (zero for pair 7)
//   c in [32,64):  dst pair p <- src pair p-1   (zero for pair 0)
//   c in [64,256): dst pair p <- src pair p
// 1568 float4 per block, 256 threads -> 6-7 front-batched independent loads
// per thread (high MLP), streaming cache hints (zero reuse).

#define P4     1568          // 2*784 float4 per t-pair
#define NPAIR  16384         // 8*256*8
#define NTH    256

__global__ void __launch_bounds__(NTH)
temporal_shift_kernel(const float4* __restrict__ x, float4* __restrict__ y) {
    int p = blockIdx.x;                 // (n*256 + c)*8 + t_pair
    int t2 = p & 7;
    int c  = (p >> 3) & 255;
    int tid = threadIdx.x;

    float4* dst = y + (long long)p * P4;
    bool extra = tid < (P4 - 6 * NTH);  // 1568 = 6*256 + 32

    const float4* src;
    bool zero = false;
    if (c < 32) {
        if (t2 < 7) src = x + (long long)(p + 1) * P4;
        else        zero = true;
    } else if (c < 64) {
        if (t2 > 0) src = x + (long long)(p - 1) * P4;
        else        zero = true;
    } else {
        src = x + (long long)p * P4;
    }

    if (zero) {
        float4 z = make_float4(0.f, 0.f, 0.f, 0.f);
        #pragma unroll
        for (int k = 0; k < 6; k++)
            __stcs(dst + tid + k * NTH, z);
        if (extra) __stcs(dst + tid + 6 * NTH, z);
        return;
    }

    // Front-batch all independent loads, then stores.
    float4 v0 = __ldcs(src + tid);
    float4 v1 = __ldcs(src + tid + 1 * NTH);
    float4 v2 = __ldcs(src + tid + 2 * NTH);
    float4 v3 = __ldcs(src + tid + 3 * NTH);
    float4 v4 = __ldcs(src + tid + 4 * NTH);
    float4 v5 = __ldcs(src + tid + 5 * NTH);
    float4 v6;
    if (extra) v6 = __ldcs(src + tid + 6 * NTH);

    __stcs(dst + tid,           v0);
    __stcs(dst + tid + 1 * NTH, v1);
    __stcs(dst + tid + 2 * NTH, v2);
    __stcs(dst + tid + 3 * NTH, v3);
    __stcs(dst + tid + 4 * NTH, v4);
    __stcs(dst + tid + 5 * NTH, v5);
    if (extra) __stcs(dst + tid + 6 * NTH, v6);
}

extern "C" void kernel_launch(void* const* d_in, const int* in_sizes, int n_in,
                              void* d_out, int out_size) {
    const float4* x = (const float4*)d_in[0];   // weight d_in[1] is fixed one-hot; semantics hardcoded
    float4* y = (float4*)d_out;
    temporal_shift_kernel<<<NPAIR, NTH>>>(x, y);
}

// round 6
// speedup vs baseline: 1.1349x; 1.0035x over previous
#include <cuda_runtime.h>

// TemporalExtensionShift: x [8, 256, 16, 56, 56] f32.
// One-hot depthwise dilated conv == temporal shift by +-2 t == one t-PAIR:
//   c in [0,32):   dst pair p <- src pair p+1   (zero for pair 7)
//   c in [32,64):  dst pair p <- src pair p-1   (zero for pair 0)
//   c in [64,256): dst pair p <- src pair p
// Block = TWO adjacent t-pairs (3136 float4), 512 threads:
// high occupancy (3 CTA/SM) AND high MLP (6-7 front-batched loads/thread).

#define P4     1568          // 2*784 float4 per t-pair
#define NB     8192          // 8*256*8 pairs / 2 pairs per block
#define NTH    512

__device__ __forceinline__ const float4* pair_src(const float4* __restrict__ x,
                                                  int p, int t2, int c) {
    // returns nullptr for zero-fill
    if (c < 32)  return (t2 < 7) ? x + (long long)(p + 1) * P4 : nullptr;
    if (c < 64)  return (t2 > 0) ? x + (long long)(p - 1) * P4 : nullptr;
    return x + (long long)p * P4;
}

__global__ void __launch_bounds__(NTH)
temporal_shift_kernel(const float4* __restrict__ x, float4* __restrict__ y) {
    int b = blockIdx.x;
    int p0 = 2 * b;                       // first pair: (n*256+c)*8 + t2
    int t2 = p0 & 7;                      // even (0,2,4,6)
    int c  = (p0 >> 3) & 255;
    int tid = threadIdx.x;

    const float4* s0 = pair_src(x, p0,     t2,     c);
    const float4* s1 = pair_src(x, p0 + 1, t2 + 1, c);
    float4* d0 = y + (long long)p0 * P4;
    float4* d1 = d0 + P4;

    bool tail = tid < (P4 - 3 * NTH);     // 1568 = 3*512 + 32
    const float4 z = make_float4(0.f, 0.f, 0.f, 0.f);

    // Front-batch all independent loads across BOTH pairs, then store.
    float4 a0 = z, a1 = z, a2 = z, a3 = z;
    float4 b0 = z, b1 = z, b2 = z, b3 = z;

    if (s0) {
        a0 = __ldcs(s0 + tid);
        a1 = __ldcs(s0 + tid + NTH);
        a2 = __ldcs(s0 + tid + 2 * NTH);
        if (tail) a3 = __ldcs(s0 + tid + 3 * NTH);
    }
    if (s1) {
        b0 = __ldcs(s1 + tid);
        b1 = __ldcs(s1 + tid + NTH);
        b2 = __ldcs(s1 + tid + 2 * NTH);
        if (tail) b3 = __ldcs(s1 + tid + 3 * NTH);
    }

    __stcs(d0 + tid,           a0);
    __stcs(d0 + tid + NTH,     a1);
    __stcs(d0 + tid + 2 * NTH, a2);
    if (tail) __stcs(d0 + tid + 3 * NTH, a3);

    __stcs(d1 + tid,           b0);
    __stcs(d1 + tid + NTH,     b1);
    __stcs(d1 + tid + 2 * NTH, b2);
    if (tail) __stcs(d1 + tid + 3 * NTH, b3);
}

extern "C" void kernel_launch(void* const* d_in, const int* in_sizes, int n_in,
                              void* d_out, int out_size) {
    const float4* x = (const float4*)d_in[0];   // weight d_in[1] is fixed one-hot; semantics hardcoded
    float4* y = (float4*)d_out;
    temporal_shift_kernel<<<NB, NTH>>>(x, y);
}